// round 1
// baseline (speedup 1.0000x reference)
#include <cuda_runtime.h>

#define N_NODES 100000
#define N_EDGES 600000
#define N_GRAPHS 512
#define DIM 128
#define N_LAYERS 3
#define BN_EPS 1e-5f

// ---------------- scratch (device globals; no allocation allowed) ----------
__device__ __align__(16) float g_AGG[(size_t)N_NODES * DIM];
__device__ __align__(16) float g_T[(size_t)N_NODES * DIM];
__device__ float g_S1[DIM], g_Q1[DIM], g_S2[DIM], g_Q2[DIM];
__device__ float g_SC1[DIM], g_SH1[DIM], g_SC2[DIM], g_SH2[DIM];
__device__ __align__(16) float g_GS[N_GRAPHS * DIM];
__device__ float g_GC[N_GRAPHS];

// ---------------- small helpers --------------------------------------------
__global__ void zero_stats_kernel() {
    int t = threadIdx.x;
    if (t < DIM) { g_S1[t] = 0.f; g_Q1[t] = 0.f; g_S2[t] = 0.f; g_Q2[t] = 0.f; }
}

__global__ void pool_zero_kernel() {
    int i = blockIdx.x * blockDim.x + threadIdx.x;
    if (i < N_GRAPHS * DIM) g_GS[i] = 0.f;
    if (i < N_GRAPHS) g_GC[i] = 0.f;
}

// AGG = Hin  (vectorized copy)
__global__ void copy_to_agg_kernel(const float* __restrict__ H) {
    int i = blockIdx.x * blockDim.x + threadIdx.x;
    if (i < N_NODES * (DIM / 4))
        reinterpret_cast<float4*>(g_AGG)[i] = reinterpret_cast<const float4*>(H)[i];
}

// AGG[dst] += H[src]   (edge-parallel, float4 vector reductions)
__global__ void scatter_add_kernel(const float* __restrict__ H,
                                   const int* __restrict__ src,
                                   const int* __restrict__ dst) {
    int idx = blockIdx.x * blockDim.x + threadIdx.x;
    if (idx >= N_EDGES * (DIM / 4)) return;
    int e = idx >> 5;          // 32 float4 chunks per edge
    int j = idx & 31;
    int s = __ldg(&src[e]);
    int d = __ldg(&dst[e]);
    float4 v = reinterpret_cast<const float4*>(H)[s * 32 + j];
    atomicAdd(reinterpret_cast<float4*>(g_AGG) + d * 32 + j, v);
}

// ---------------- GEMM + column-stats  --------------------------------------
// PHASE 1: T  = AGG @ W + b        (accumulate col sum/sumsq into S1/Q1)
// PHASE 2: AGG = BN1(T) @ W + b    (affine sc1/sh1 applied to A on load;
//                                   stats into S2/Q2)
// Tile: 64 rows x 128 cols per 256-thread block; thread = 8 rows x 4 cols.
template <int PHASE>
__global__ void __launch_bounds__(256) gemm_bn_kernel(const float* __restrict__ W,
                                                      const float* __restrict__ bias) {
    const float* A  = (PHASE == 1) ? g_AGG : g_T;
    float*       Out = (PHASE == 1) ? g_T : g_AGG;
    float*       Sg  = (PHASE == 1) ? g_S1 : g_S2;
    float*       Qg  = (PHASE == 1) ? g_Q1 : g_Q2;

    __shared__ float Ws[32 * DIM];   // one K-chunk of W: [kk][n]
    __shared__ float As[64 * 32];    // A tile chunk:     [row][kk]
    __shared__ float sS[DIM], sQ[DIM];
    __shared__ float sScl[DIM], sShf[DIM];

    int tid = threadIdx.x;
    int tx = tid & 31;         // column group: cols [4*tx, 4*tx+4)
    int ty = tid >> 5;         // row group:    rows [8*ty, 8*ty+8)
    int row0 = blockIdx.x * 64;

    if (tid < DIM) {
        sS[tid] = 0.f; sQ[tid] = 0.f;
        if (PHASE == 2) { sScl[tid] = g_SC1[tid]; sShf[tid] = g_SH1[tid]; }
    }

    float4 bv = reinterpret_cast<const float4*>(bias)[tx];
    float acc[8][4];
#pragma unroll
    for (int r = 0; r < 8; r++) {
        acc[r][0] = bv.x; acc[r][1] = bv.y; acc[r][2] = bv.z; acc[r][3] = bv.w;
    }

    for (int kc = 0; kc < 4; kc++) {
        __syncthreads();
        // load W chunk: 32 x 128 floats = 1024 float4
#pragma unroll
        for (int i = 0; i < 4; i++) {
            int idx = tid + i * 256;
            reinterpret_cast<float4*>(Ws)[idx] =
                reinterpret_cast<const float4*>(W)[kc * 1024 + idx];
        }
        // load A chunk: 64 rows x 32 k = 512 float4
#pragma unroll
        for (int i = 0; i < 2; i++) {
            int idx = tid + i * 256;
            int r = idx >> 3, kq = idx & 7;
            int grow = row0 + r;
            float4 v = make_float4(0.f, 0.f, 0.f, 0.f);
            if (grow < N_NODES)
                v = reinterpret_cast<const float4*>(A)[grow * 32 + kc * 8 + kq];
            if (PHASE == 2) {
                int kb = kc * 32 + kq * 4;
                v.x = fmaf(v.x, sScl[kb + 0], sShf[kb + 0]);
                v.y = fmaf(v.y, sScl[kb + 1], sShf[kb + 1]);
                v.z = fmaf(v.z, sScl[kb + 2], sShf[kb + 2]);
                v.w = fmaf(v.w, sScl[kb + 3], sShf[kb + 3]);
            }
            reinterpret_cast<float4*>(As)[idx] = v;
        }
        __syncthreads();
#pragma unroll 8
        for (int kk = 0; kk < 32; kk++) {
            float4 w4 = reinterpret_cast<float4*>(Ws)[kk * 32 + tx];
            float a_[8];
#pragma unroll
            for (int r = 0; r < 8; r++) a_[r] = As[(ty * 8 + r) * 32 + kk];
#pragma unroll
            for (int r = 0; r < 8; r++) {
                acc[r][0] = fmaf(a_[r], w4.x, acc[r][0]);
                acc[r][1] = fmaf(a_[r], w4.y, acc[r][1]);
                acc[r][2] = fmaf(a_[r], w4.z, acc[r][2]);
                acc[r][3] = fmaf(a_[r], w4.w, acc[r][3]);
            }
        }
    }

    // epilogue: store + per-column partial stats (only valid rows)
    float s[4] = {0.f, 0.f, 0.f, 0.f}, q[4] = {0.f, 0.f, 0.f, 0.f};
#pragma unroll
    for (int r = 0; r < 8; r++) {
        int grow = row0 + ty * 8 + r;
        if (grow < N_NODES) {
            float4 o = make_float4(acc[r][0], acc[r][1], acc[r][2], acc[r][3]);
            reinterpret_cast<float4*>(Out)[grow * 32 + tx] = o;
#pragma unroll
            for (int c = 0; c < 4; c++) { s[c] += acc[r][c]; q[c] += acc[r][c] * acc[r][c]; }
        }
    }
#pragma unroll
    for (int c = 0; c < 4; c++) {
        atomicAdd(&sS[tx * 4 + c], s[c]);
        atomicAdd(&sQ[tx * 4 + c], q[c]);
    }
    __syncthreads();
    if (tid < DIM) { atomicAdd(&Sg[tid], sS[tid]); atomicAdd(&Qg[tid], sQ[tid]); }
}

// BN1 -> scale/shift
__global__ void stats1_kernel(const float* __restrict__ g, const float* __restrict__ bt) {
    int t = threadIdx.x;
    const float invN = 1.0f / (float)N_NODES;
    float m = g_S1[t] * invN;
    float v = fmaxf(g_Q1[t] * invN - m * m, 0.f);
    float r = rsqrtf(v + BN_EPS);
    float sc = r * g[t];
    g_SC1[t] = sc;
    g_SH1[t] = bt[t] - m * sc;
}

// BN2 folded with BN3 (outer): BN3(BN2(x)) = (x - m2) * total + bo
// where total = r2 * g2 * go * rsqrt(g2^2 * v2/(v2+eps) + eps)
__global__ void stats2_kernel(const float* __restrict__ g2,
                              const float* __restrict__ go,
                              const float* __restrict__ bo) {
    int t = threadIdx.x;
    const float invN = 1.0f / (float)N_NODES;
    float m = g_S2[t] * invN;
    float v = fmaxf(g_Q2[t] * invN - m * m, 0.f);
    float r2 = rsqrtf(v + BN_EPS);
    float gg = g2[t];
    float vy = gg * gg * v * r2 * r2;            // exact var of BN2 output
    float sc3 = rsqrtf(vy + BN_EPS) * go[t];
    float total = r2 * gg * sc3;
    g_SC2[t] = total;
    g_SH2[t] = bo[t] - m * total;
}

// H = relu(AGG * sc2 + sh2)
__global__ void apply_relu_kernel(float* __restrict__ H) {
    int i = blockIdx.x * blockDim.x + threadIdx.x;
    if (i >= N_NODES * (DIM / 4)) return;
    int k = (i & 31) * 4;
    float4 v = reinterpret_cast<float4*>(g_AGG)[i];
    v.x = fmaxf(fmaf(v.x, g_SC2[k + 0], g_SH2[k + 0]), 0.f);
    v.y = fmaxf(fmaf(v.y, g_SC2[k + 1], g_SH2[k + 1]), 0.f);
    v.z = fmaxf(fmaf(v.z, g_SC2[k + 2], g_SH2[k + 2]), 0.f);
    v.w = fmaxf(fmaf(v.w, g_SC2[k + 3], g_SH2[k + 3]), 0.f);
    reinterpret_cast<float4*>(H)[i] = v;
}

// ---------------- pooling + classifier -------------------------------------
__global__ void pool_scatter_kernel(const float* __restrict__ H,
                                    const int* __restrict__ batch) {
    int idx = blockIdx.x * blockDim.x + threadIdx.x;
    if (idx >= N_NODES * (DIM / 4)) return;
    int n = idx >> 5, j = idx & 31;
    int gidx = __ldg(&batch[n]);
    float4 v = reinterpret_cast<const float4*>(H)[n * 32 + j];
    atomicAdd(reinterpret_cast<float4*>(g_GS) + gidx * 32 + j, v);
}

__global__ void pool_counts_kernel(const int* __restrict__ batch) {
    int n = blockIdx.x * blockDim.x + threadIdx.x;
    if (n < N_NODES) atomicAdd(&g_GC[batch[n]], 1.0f);
}

__global__ void graph_fc_kernel(const float* __restrict__ fcW,
                                const float* __restrict__ fcb,
                                float* __restrict__ Gout,
                                float* __restrict__ Cout) {
    int g = blockIdx.x;
    int t = threadIdx.x;   // 128
    float cnt = fmaxf(g_GC[g], 1.0f);
    float ge = g_GS[g * DIM + t] / cnt;
    Gout[g * DIM + t] = ge;
    __shared__ float r0[DIM], r1[DIM];
    r0[t] = ge * fcW[t * 2 + 0];
    r1[t] = ge * fcW[t * 2 + 1];
    __syncthreads();
    for (int s = 64; s > 0; s >>= 1) {
        if (t < s) { r0[t] += r0[t + s]; r1[t] += r1[t + s]; }
        __syncthreads();
    }
    if (t == 0) {
        Cout[g * 2 + 0] = r0[0] + fcb[0];
        Cout[g * 2 + 1] = r1[0] + fcb[1];
    }
}

// ---------------- launcher ---------------------------------------------------
extern "C" void kernel_launch(void* const* d_in, const int* in_sizes, int n_in,
                              void* d_out, int out_size) {
    const float* x    = (const float*)d_in[0];
    const int*   ei   = (const int*)d_in[1];
    const int*   batch= (const int*)d_in[2];
    const float* W1   = (const float*)d_in[3];
    const float* b1   = (const float*)d_in[4];
    const float* g1   = (const float*)d_in[5];
    const float* bt1  = (const float*)d_in[6];
    const float* W2   = (const float*)d_in[7];
    const float* b2   = (const float*)d_in[8];
    const float* g2   = (const float*)d_in[9];
    // const float* bt2 = (const float*)d_in[10];  // cancels analytically in BN2∘BN3
    const float* go   = (const float*)d_in[11];
    const float* bo   = (const float*)d_in[12];
    const float* fcW  = (const float*)d_in[13];
    const float* fcb  = (const float*)d_in[14];

    float* out  = (float*)d_out;
    float* Hout = out;                               // node embeddings
    float* Gout = out + (size_t)N_NODES * DIM;       // graph embedding
    float* Cout = Gout + (size_t)N_GRAPHS * DIM;     // classifier output

    const int* src = ei;
    const int* dst = ei + N_EDGES;

    const int nCopyBlocks    = (N_NODES * (DIM / 4)) / 256;      // 12500
    const int nScatterBlocks = (N_EDGES * (DIM / 4)) / 256;      // 75000
    const int nGemmBlocks    = (N_NODES + 63) / 64;              // 1563

    for (int i = 0; i < N_LAYERS; i++) {
        const float* Hin = (i == 0) ? x : Hout;
        zero_stats_kernel<<<1, 128>>>();
        copy_to_agg_kernel<<<nCopyBlocks, 256>>>(Hin);
        scatter_add_kernel<<<nScatterBlocks, 256>>>(Hin, src, dst);
        gemm_bn_kernel<1><<<nGemmBlocks, 256>>>(W1 + (size_t)i * DIM * DIM, b1 + i * DIM);
        stats1_kernel<<<1, 128>>>(g1 + i * DIM, bt1 + i * DIM);
        gemm_bn_kernel<2><<<nGemmBlocks, 256>>>(W2 + (size_t)i * DIM * DIM, b2 + i * DIM);
        stats2_kernel<<<1, 128>>>(g2 + i * DIM, go + i * DIM, bo + i * DIM);
        apply_relu_kernel<<<nCopyBlocks, 256>>>(Hout);
    }

    pool_zero_kernel<<<(N_GRAPHS * DIM) / 256, 256>>>();
    pool_scatter_kernel<<<nCopyBlocks, 256>>>(Hout, batch);
    pool_counts_kernel<<<(N_NODES + 255) / 256, 256>>>(batch);
    graph_fc_kernel<<<N_GRAPHS, DIM>>>(fcW, fcb, Gout, Cout);
}